// round 6
// baseline (speedup 1.0000x reference)
#include <cuda_runtime.h>
#include <cstdint>

typedef unsigned long long u64;

__device__ float g_bufA[8388608];
__device__ float g_bufB[4194304];
__device__ float g_wT [21971520];   // transposed weights [c][ij][o], all 14 layers packed

__device__ __forceinline__ void cp_async16(uint32_t saddr, const float* gptr) {
    asm volatile("cp.async.cg.shared.global [%0], [%1], 16;" :: "r"(saddr), "l"(gptr));
}
#define CP_COMMIT() asm volatile("cp.async.commit_group;" ::: "memory")
#define CP_WAIT0()  asm volatile("cp.async.wait_group 0;" ::: "memory")
#define FFMA2(acc, w, v) asm("fma.rn.f32x2 %0, %1, %2, %0;" : "+l"(acc) : "l"(w), "l"(v))
#define PACK2(d, a, b)   asm("mov.b64 %0, {%1, %2};" : "=l"(d) : "f"(a), "f"(b))
#define UNPACK2(lo, hi, p) asm("mov.b64 {%0, %1}, %2;" : "=f"(lo), "=f"(hi) : "l"(p))

// ─── fused weight transpose: one launch for all 14 layers ───
struct WPtrs { const float* p[14]; };

__global__ void transpose_all_kernel(WPtrs wp, float* __restrict__ wt)
{
    const int i = blockIdx.x * 256 + threadIdx.x;
    if (i >= 21971520) return;
    // compile-time tables
    const int CiA[14] = {1,64,64, 64,128,128, 128,256,256, 256,512,512, 512,1024};
    const int CoA[14] = {64,64,64, 128,128,128, 256,256,256, 512,512,512, 1024,1024};
    const int OFF[15] = {0,576,37440,74304,148032,295488,442944,737856,1327680,
                         1917504,3097152,5456448,7815744,12534336,21971520};
    int l = 0;
    #pragma unroll
    for (int k = 1; k < 14; k++) if (i >= OFF[k]) l = k;
    int j = i - OFF[l];
    int Co = CoA[l], Ci = CiA[l];
    int o = j % Co;
    int cij = j / Co;
    int c = cij / 9, ij = cij % 9;
    wt[i] = wp.p[l][((size_t)o * Ci + c) * 9 + ij];
}

// ─── stride-1, wide images (W>=32): 32x8 tile, 1 px/thread, 8 outs, conflict-free LDS ───
template<int CB>
__global__ void __launch_bounds__(256) conv_s1(
    const float* __restrict__ in, const float* __restrict__ wt,
    const float* __restrict__ bias, const float* __restrict__ kern,
    float* __restrict__ out, int Ci, int Co, int H, int W, int tilesX)
{
    constexpr int ROWS = 10, PITCH = 40, CSZ = ROWS * PITCH;   // 400
    constexpr int ISLOTS = CB * ROWS * 10;
    constexpr int NIT = (ISLOTS + 255) / 256;
    __shared__ __align__(16) float s_in[2][CB * CSZ];
    __shared__ __align__(16) float s_w[2][CB * 72];   // [c][ij][8]

    const int tid = threadIdx.x;
    const int tx = tid & 31, ty = tid >> 5;
    const int tX = blockIdx.x % tilesX, tY = blockIdx.x / tilesX;
    const int ocg = blockIdx.y, b = blockIdx.z;
    const int oh = tY * 8 + ty, ow = tX * 32 + tx;
    const size_t HW = (size_t)H * W;

    float kreg[9];
    if (kern) {
        const float* kp = kern + (size_t)b * 9 * HW + (size_t)oh * W + ow;
        #pragma unroll
        for (int t = 0; t < 9; t++) kreg[t] = kp[(size_t)t * HW];
    } else {
        #pragma unroll
        for (int t = 0; t < 9; t++) kreg[t] = 1.0f;
    }

    u64 acc[4];
    #pragma unroll
    for (int p = 0; p < 4; p++) acc[p] = 0ull;

    for (int i = tid; i < 2 * CB * CSZ; i += 256) (&s_in[0][0])[i] = 0.0f;
    __syncthreads();

    const uint32_t sinA[2] = {(uint32_t)__cvta_generic_to_shared(&s_in[0][0]),
                              (uint32_t)__cvta_generic_to_shared(&s_in[1][0])};
    const uint32_t swA[2]  = {(uint32_t)__cvta_generic_to_shared(&s_w[0][0]),
                              (uint32_t)__cvta_generic_to_shared(&s_w[1][0])};
    const int NG = Ci / CB;
    const int gr0 = tY * 8 - 1;
    const int gc0 = tX * 32 - 4;

    // Hoisted staging descriptors
    const float* gsrc[NIT];
    uint32_t soff[NIT];
    bool sval[NIT];
    {
        const float* ib0 = in + (size_t)b * Ci * HW;
        #pragma unroll
        for (int k = 0; k < NIT; k++) {
            int slot = tid + k * 256;
            int c = slot / 100, rem = slot % 100;
            int r = rem / 10, q = rem % 10;
            int gr = gr0 + r, gc = gc0 + 4 * q;
            sval[k] = (slot < ISLOTS) && ((unsigned)gr < (unsigned)H) &&
                      (gc >= 0) && (gc + 4 <= W);
            soff[k] = (uint32_t)(c * CSZ + r * PITCH + 4 * q) * 4u;
            gsrc[k] = ib0 + (size_t)c * HW + (size_t)gr * W + gc;
        }
    }
    const bool wval = tid < CB * 18;
    uint32_t woff = 0;
    const float* wsrc = wt;
    {
        int c = tid / 18, rem = tid % 18, ij = rem / 2, q = rem % 2;
        woff = (uint32_t)(c * 72 + ij * 8 + 4 * q) * 4u;
        wsrc = wt + ((size_t)c * 9 + ij) * Co + (size_t)ocg * 8 + 4 * q;
    }
    const size_t gstep = (size_t)CB * HW;
    const size_t wstep = (size_t)CB * 9 * Co;

    auto stage = [&](int buf) {
        #pragma unroll
        for (int k = 0; k < NIT; k++) {
            if (sval[k]) cp_async16(sinA[buf] + soff[k], gsrc[k]);
            gsrc[k] += gstep;
        }
        if (wval) { cp_async16(swA[buf] + woff, wsrc); }
        wsrc += wstep;
    };

    stage(0);
    CP_COMMIT();

    const int base_off = ty * PITCH + tx + 3;

    for (int cg = 0; cg < NG; cg++) {
        CP_WAIT0();
        __syncthreads();
        if (cg + 1 < NG) { stage((cg + 1) & 1); CP_COMMIT(); }
        const int buf = cg & 1;

        #pragma unroll
        for (int c = 0; c < CB; c++) {
            const float* sp = &s_in[buf][c * CSZ + base_off];
            const ulonglong2* wp = reinterpret_cast<const ulonglong2*>(&s_w[buf][c * 72]);
            #pragma unroll
            for (int t = 0; t < 9; t++) {
                float v = sp[(t / 3) * PITCH + (t % 3)] * kreg[t];
                u64 vv;
                PACK2(vv, v, v);
                ulonglong2 wa = wp[2 * t];
                ulonglong2 wbv = wp[2 * t + 1];
                FFMA2(acc[0], wa.x,  vv); FFMA2(acc[1], wa.y,  vv);
                FFMA2(acc[2], wbv.x, vv); FFMA2(acc[3], wbv.y, vv);
            }
        }
    }

    #pragma unroll
    for (int p = 0; p < 4; p++) {
        int o = ocg * 8 + 2 * p;
        float lo, hi;
        UNPACK2(lo, hi, acc[p]);
        float v0 = lo + bias[o], v1 = hi + bias[o + 1];
        v0 = v0 > 0.0f ? v0 : 0.0f;
        v1 = v1 > 0.0f ? v1 : 0.0f;
        out[((size_t)(b * Co + o)     * H + oh) * W + ow] = v0;
        out[((size_t)(b * Co + o + 1) * H + oh) * W + ow] = v1;
    }
}

// ─── stride-1, 16x16 images: whole image per block, PITCH=48 (conflict-free), CB=4 ───
__global__ void __launch_bounds__(256) conv_s1_16(
    const float* __restrict__ in, const float* __restrict__ wt,
    const float* __restrict__ bias, const float* __restrict__ kern,
    float* __restrict__ out, int Ci, int Co)
{
    constexpr int CB = 4, ROWS = 18, PITCH = 48, CSZ = ROWS * PITCH;  // 864
    constexpr int ISLOTS = CB * ROWS * 6;   // 432
    constexpr int NIT = 2;
    __shared__ __align__(16) float s_in[2][CB * CSZ];
    __shared__ __align__(16) float s_w[2][CB * 72];

    const int tid = threadIdx.x;
    const int tx = tid % 16, ty = tid / 16;
    const int ocg = blockIdx.y, b = blockIdx.z;
    const size_t HW = 256;

    float kreg[9];
    {
        const float* kp = kern + (size_t)b * 9 * HW + (size_t)ty * 16 + tx;
        #pragma unroll
        for (int t = 0; t < 9; t++) kreg[t] = kp[(size_t)t * HW];
    }

    u64 acc[4];
    #pragma unroll
    for (int p = 0; p < 4; p++) acc[p] = 0ull;

    for (int i = tid; i < 2 * CB * CSZ; i += 256) (&s_in[0][0])[i] = 0.0f;
    __syncthreads();

    const uint32_t sinA[2] = {(uint32_t)__cvta_generic_to_shared(&s_in[0][0]),
                              (uint32_t)__cvta_generic_to_shared(&s_in[1][0])};
    const uint32_t swA[2]  = {(uint32_t)__cvta_generic_to_shared(&s_w[0][0]),
                              (uint32_t)__cvta_generic_to_shared(&s_w[1][0])};
    const int NG = Ci / CB;

    const float* gsrc[NIT];
    uint32_t soff[NIT];
    bool sval[NIT];
    {
        const float* ib0 = in + (size_t)b * Ci * HW;
        #pragma unroll
        for (int k = 0; k < NIT; k++) {
            int slot = tid + k * 256;
            int c = slot / 108, rem = slot % 108;
            int r = rem / 6, q = rem % 6;
            int gr = r - 1, gc = 4 * q - 4;
            sval[k] = (slot < ISLOTS) && ((unsigned)gr < 16u) && (gc >= 0) && (gc + 4 <= 16);
            soff[k] = (uint32_t)(c * CSZ + r * PITCH + 4 * q) * 4u;
            gsrc[k] = ib0 + (size_t)c * HW + (size_t)gr * 16 + gc;
        }
    }
    const bool wval = tid < CB * 18;
    uint32_t woff = 0;
    const float* wsrc = wt;
    {
        int c = tid / 18, rem = tid % 18, ij = rem / 2, q = rem % 2;
        woff = (uint32_t)(c * 72 + ij * 8 + 4 * q) * 4u;
        wsrc = wt + ((size_t)c * 9 + ij) * Co + (size_t)ocg * 8 + 4 * q;
    }
    const size_t gstep = (size_t)CB * HW;
    const size_t wstep = (size_t)CB * 9 * Co;

    auto stage = [&](int buf) {
        #pragma unroll
        for (int k = 0; k < NIT; k++) {
            if (sval[k]) cp_async16(sinA[buf] + soff[k], gsrc[k]);
            gsrc[k] += gstep;
        }
        if (wval) { cp_async16(swA[buf] + woff, wsrc); }
        wsrc += wstep;
    };

    stage(0);
    CP_COMMIT();

    const int base_off = ty * PITCH + tx + 3;

    for (int cg = 0; cg < NG; cg++) {
        CP_WAIT0();
        __syncthreads();
        if (cg + 1 < NG) { stage((cg + 1) & 1); CP_COMMIT(); }
        const int buf = cg & 1;

        #pragma unroll
        for (int c = 0; c < CB; c++) {
            const float* sp = &s_in[buf][c * CSZ + base_off];
            const ulonglong2* wp = reinterpret_cast<const ulonglong2*>(&s_w[buf][c * 72]);
            #pragma unroll
            for (int t = 0; t < 9; t++) {
                float v = sp[(t / 3) * PITCH + (t % 3)] * kreg[t];
                u64 vv;
                PACK2(vv, v, v);
                ulonglong2 wa = wp[2 * t];
                ulonglong2 wbv = wp[2 * t + 1];
                FFMA2(acc[0], wa.x,  vv); FFMA2(acc[1], wa.y,  vv);
                FFMA2(acc[2], wbv.x, vv); FFMA2(acc[3], wbv.y, vv);
            }
        }
    }

    #pragma unroll
    for (int p = 0; p < 4; p++) {
        int o = ocg * 8 + 2 * p;
        float lo, hi;
        UNPACK2(lo, hi, acc[p]);
        float v0 = lo + bias[o], v1 = hi + bias[o + 1];
        v0 = v0 > 0.0f ? v0 : 0.0f;
        v1 = v1 > 0.0f ? v1 : 0.0f;
        out[((size_t)(b * Co + o)     * 16 + ty) * 16 + tx] = v0;
        out[((size_t)(b * Co + o + 1) * 16 + ty) * 16 + tx] = v1;
    }
}

// ─── stride-2: 16x16 output tile, 1 px/thread, 8 outputs, CB=2 ───
__global__ void __launch_bounds__(256) conv_s2(
    const float* __restrict__ in, const float* __restrict__ wt,
    const float* __restrict__ bias, const float* __restrict__ kern,
    float* __restrict__ out, int Ci, int Co, int H, int W, int tilesX)
{
    constexpr int CB = 2, ROWS = 33, PITCH = 40, CSZ = ROWS * PITCH;
    constexpr int ISLOTS = CB * ROWS * 10;   // 660
    constexpr int NIT = 3;
    __shared__ __align__(16) float s_in[2][CB * CSZ];
    __shared__ __align__(16) float s_w[2][CB * 72];

    const int tid = threadIdx.x;
    const int tx = tid % 16, ty = tid / 16;
    const int tX = blockIdx.x % tilesX, tY = blockIdx.x / tilesX;
    const int ocg = blockIdx.y, b = blockIdx.z;
    const int Hout = H / 2, Wout = W / 2;
    const int oh = tY * 16 + ty, ow = tX * 16 + tx;
    const size_t HW = (size_t)H * W;

    float kreg[9];
    if (kern) {
        const float* kp = kern + (size_t)b * 9 * HW + (size_t)(oh * 2) * W + ow * 2;
        #pragma unroll
        for (int t = 0; t < 9; t++) kreg[t] = kp[(size_t)t * HW];
    } else {
        #pragma unroll
        for (int t = 0; t < 9; t++) kreg[t] = 1.0f;
    }

    u64 acc[4];
    #pragma unroll
    for (int p = 0; p < 4; p++) acc[p] = 0ull;

    for (int i = tid; i < 2 * CB * CSZ; i += 256) (&s_in[0][0])[i] = 0.0f;
    __syncthreads();

    const uint32_t sinA[2] = {(uint32_t)__cvta_generic_to_shared(&s_in[0][0]),
                              (uint32_t)__cvta_generic_to_shared(&s_in[1][0])};
    const uint32_t swA[2]  = {(uint32_t)__cvta_generic_to_shared(&s_w[0][0]),
                              (uint32_t)__cvta_generic_to_shared(&s_w[1][0])};
    const int NG = Ci / CB;
    const int gr0 = tY * 32 - 1;
    const int gc0 = tX * 32 - 4;

    const float* gsrc[NIT];
    uint32_t soff[NIT];
    bool sval[NIT];
    {
        const float* ib0 = in + (size_t)b * Ci * HW;
        #pragma unroll
        for (int k = 0; k < NIT; k++) {
            int slot = tid + k * 256;
            int c = slot / 330, rem = slot % 330;
            int r = rem / 10, q = rem % 10;
            int gr = gr0 + r, gc = gc0 + 4 * q;
            sval[k] = (slot < ISLOTS) && ((unsigned)gr < (unsigned)H) &&
                      (gc >= 0) && (gc + 4 <= W);
            soff[k] = (uint32_t)(c * CSZ + r * PITCH + 4 * q) * 4u;
            gsrc[k] = ib0 + (size_t)c * HW + (size_t)gr * W + gc;
        }
    }
    const bool wval = tid < CB * 18;
    uint32_t woff = 0;
    const float* wsrc = wt;
    {
        int c = tid / 18, rem = tid % 18, ij = rem / 2, q = rem % 2;
        woff = (uint32_t)(c * 72 + ij * 8 + 4 * q) * 4u;
        wsrc = wt + ((size_t)c * 9 + ij) * Co + (size_t)ocg * 8 + 4 * q;
    }
    const size_t gstep = (size_t)CB * HW;
    const size_t wstep = (size_t)CB * 9 * Co;

    auto stage = [&](int buf) {
        #pragma unroll
        for (int k = 0; k < NIT; k++) {
            if (sval[k]) cp_async16(sinA[buf] + soff[k], gsrc[k]);
            gsrc[k] += gstep;
        }
        if (wval) { cp_async16(swA[buf] + woff, wsrc); }
        wsrc += wstep;
    };

    stage(0);
    CP_COMMIT();

    const int base_off = (2 * ty) * PITCH + 2 * tx + 3;

    for (int cg = 0; cg < NG; cg++) {
        CP_WAIT0();
        __syncthreads();
        if (cg + 1 < NG) { stage((cg + 1) & 1); CP_COMMIT(); }
        const int buf = cg & 1;

        #pragma unroll
        for (int c = 0; c < CB; c++) {
            const float* sp = &s_in[buf][c * CSZ + base_off];
            const ulonglong2* wp = reinterpret_cast<const ulonglong2*>(&s_w[buf][c * 72]);
            #pragma unroll
            for (int t = 0; t < 9; t++) {
                float v = sp[(t / 3) * PITCH + (t % 3)] * kreg[t];
                u64 vv;
                PACK2(vv, v, v);
                ulonglong2 wa = wp[2 * t];
                ulonglong2 wbv = wp[2 * t + 1];
                FFMA2(acc[0], wa.x,  vv); FFMA2(acc[1], wa.y,  vv);
                FFMA2(acc[2], wbv.x, vv); FFMA2(acc[3], wbv.y, vv);
            }
        }
    }

    #pragma unroll
    for (int p = 0; p < 4; p++) {
        int o = ocg * 8 + 2 * p;
        float lo, hi;
        UNPACK2(lo, hi, acc[p]);
        float v0 = lo + bias[o], v1 = hi + bias[o + 1];
        v0 = v0 > 0.0f ? v0 : 0.0f;
        v1 = v1 > 0.0f ? v1 : 0.0f;
        out[((size_t)(b * Co + o)     * Hout + oh) * Wout + ow] = v0;
        out[((size_t)(b * Co + o + 1) * Hout + oh) * Wout + ow] = v1;
    }
}

__global__ void pac_gauss_kernel(const float* __restrict__ f, float* __restrict__ out,
                                 int C, int H, int W, float coeff2)
{
    const int b = blockIdx.z;
    const int idx = blockIdx.x * blockDim.x + threadIdx.x;
    if (idx >= H * W) return;
    const int h = idx / W, w = idx % W;

    float acc[9];
    #pragma unroll
    for (int t = 0; t < 9; t++) acc[t] = 0.0f;

    const float* fb = f + (size_t)b * C * H * W;
    for (int c = 0; c < C; c++) {
        const float* fc = fb + (size_t)c * H * W;
        float ctr = fc[idx];
        #pragma unroll
        for (int i = 0; i < 3; i++)
        #pragma unroll
        for (int j = 0; j < 3; j++) {
            int hh = h + i - 1, ww = w + j - 1;
            float nb = (hh >= 0 && hh < H && ww >= 0 && ww < W) ? fc[hh * W + ww] : 0.0f;
            float d = nb - ctr;
            acc[i * 3 + j] += d * d;
        }
    }

    float* ob = out + (size_t)b * 9 * H * W;
    #pragma unroll
    for (int t = 0; t < 9; t++)
        ob[(size_t)t * H * W + idx] = expf(-0.5f * coeff2 * acc[t]);
}

// ─── host side ───

static void conv_s1_l(const float* in, const float* wt, const float* b, const float* kern,
                      float* out, int Ci, int Co, int H, int W)
{
    if (W >= 32) {
        int tilesX = W / 32;
        dim3 grid(tilesX * (H / 8), Co / 8, 2);
        if (Ci % 8 == 0)
            conv_s1<8><<<grid, 256>>>(in, wt, b, kern, out, Ci, Co, H, W, tilesX);
        else
            conv_s1<1><<<grid, 256>>>(in, wt, b, kern, out, Ci, Co, H, W, tilesX);
    } else {
        dim3 grid(1, Co / 8, 2);
        conv_s1_16<<<grid, 256>>>(in, wt, b, kern, out, Ci, Co);
    }
}

static void conv_s2_l(const float* in, const float* wt, const float* b, const float* kern,
                      float* out, int Ci, int Co, int H, int W)
{
    int tilesX = W / 32;
    dim3 grid(tilesX * (H / 32), Co / 8, 2);
    conv_s2<<<grid, 256>>>(in, wt, b, kern, out, Ci, Co, H, W, tilesX);
}

static void pac_layer(const float* f, float* out, int C, int H, int W, float coeff2)
{
    int hw = H * W;
    dim3 grid((hw + 255) / 256, 1, 2);
    pac_gauss_kernel<<<grid, 256>>>(f, out, C, H, W, coeff2);
}

extern "C" void kernel_launch(void* const* d_in, const int* in_sizes, int n_in,
                              void* d_out, int out_size)
{
    const float* x = (const float*)d_in[0];
    WPtrs wp;
    const float* B14[14];
    for (int i = 0; i < 14; i++) {
        wp.p[i] = (const float*)d_in[1 + 2 * i];
        B14[i]  = (const float*)d_in[2 + 2 * i];
    }

    float* bufA; float* bufB; float* wT;
    cudaGetSymbolAddress((void**)&bufA, g_bufA);
    cudaGetSymbolAddress((void**)&bufB, g_bufB);
    cudaGetSymbolAddress((void**)&wT,  g_wT);

    static const size_t OFF[15] = {0,576,37440,74304,148032,295488,442944,737856,1327680,
                                   1917504,3097152,5456448,7815744,12534336,21971520};
    const float* wt[14];
    for (int l = 0; l < 14; l++) wt[l] = wT + OFF[l];

    transpose_all_kernel<<<(21971520 + 255) / 256, 256>>>(wp, wT);

    float* out = (float*)d_out;
    float* h1 = out;
    float* h2 = h1 + 8388608;
    float* h3 = h2 + 4194304;
    float* h4 = h3 + 2097152;
    float* h5 = h4 + 1048576;
    float* k2 = h5 + 524288;
    float* k3 = k2 + 294912;
    float* k4 = k3 + 73728;
    float* k5 = k4 + 18432;

    const float KC2 = 1e-4f * 1e-4f;

    // Stage 1
    conv_s1_l(x,    wt[0], B14[0], nullptr, bufA, 1,  64, 256, 256);
    conv_s1_l(bufA, wt[1], B14[1], nullptr, h1,   64, 64, 256, 256);
    conv_s2_l(h1,   wt[2], B14[2], nullptr, bufA, 64, 64, 256, 256);   // -> 2,64,128,128

    // Stage 2
    pac_layer(bufA, k2, 64, 128, 128, KC2);
    conv_s1_l(bufA, wt[3], B14[3], k2, bufB, 64,  128, 128, 128);
    conv_s1_l(bufB, wt[4], B14[4], k2, h2,   128, 128, 128, 128);
    conv_s2_l(h2,   wt[5], B14[5], k2, bufA, 128, 128, 128, 128);      // -> 2,128,64,64

    // Stage 3
    pac_layer(bufA, k3, 128, 64, 64, KC2);
    conv_s1_l(bufA, wt[6], B14[6], k3, bufB, 128, 256, 64, 64);
    conv_s1_l(bufB, wt[7], B14[7], k3, h3,   256, 256, 64, 64);
    conv_s2_l(h3,   wt[8], B14[8], k3, bufA, 256, 256, 64, 64);        // -> 2,256,32,32

    // Stage 4 (guidance h4*2 -> coeff^2 = 4)
    pac_layer(bufA, k4, 256, 32, 32, 4.0f);
    conv_s1_l(bufA, wt[9],  B14[9],  k4, bufB, 256, 512, 32, 32);
    conv_s1_l(bufB, wt[10], B14[10], k4, h4,   512, 512, 32, 32);
    conv_s2_l(h4,   wt[11], B14[11], k4, bufA, 512, 512, 32, 32);      // -> 2,512,16,16

    // Stage 5
    pac_layer(bufA, k5, 512, 16, 16, KC2);
    conv_s1_l(bufA, wt[12], B14[12], k5, bufB, 512,  1024, 16, 16);
    conv_s1_l(bufB, wt[13], B14[13], k5, h5,   1024, 1024, 16, 16);
}

// round 7
// speedup vs baseline: 1.1763x; 1.1763x over previous
#include <cuda_runtime.h>
#include <cstdint>

typedef unsigned long long u64;

__device__ float g_bufA[8388608];
__device__ float g_bufB[4194304];
__device__ float g_wT [21971520];   // transposed weights [c][ij][o], all 14 layers packed

__device__ __forceinline__ void cp_async16(uint32_t saddr, const float* gptr) {
    asm volatile("cp.async.cg.shared.global [%0], [%1], 16;" :: "r"(saddr), "l"(gptr));
}
#define CP_COMMIT() asm volatile("cp.async.commit_group;" ::: "memory")
#define CP_WAIT0()  asm volatile("cp.async.wait_group 0;" ::: "memory")
#define FFMA2(acc, w, v) asm("fma.rn.f32x2 %0, %1, %2, %0;" : "+l"(acc) : "l"(w), "l"(v))
#define PACK2(d, a, b)   asm("mov.b64 %0, {%1, %2};" : "=l"(d) : "f"(a), "f"(b))
#define UNPACK2(lo, hi, p) asm("mov.b64 {%0, %1}, %2;" : "=f"(lo), "=f"(hi) : "l"(p))

// ─── fused weight transpose: one launch for all 14 layers ───
struct WPtrs { const float* p[14]; };

__global__ void transpose_all_kernel(WPtrs wp, float* __restrict__ wt)
{
    const int i = blockIdx.x * 256 + threadIdx.x;
    if (i >= 21971520) return;
    const int CiA[14] = {1,64,64, 64,128,128, 128,256,256, 256,512,512, 512,1024};
    const int CoA[14] = {64,64,64, 128,128,128, 256,256,256, 512,512,512, 1024,1024};
    const int OFF[15] = {0,576,37440,74304,148032,295488,442944,737856,1327680,
                         1917504,3097152,5456448,7815744,12534336,21971520};
    int l = 0;
    #pragma unroll
    for (int k = 1; k < 14; k++) if (i >= OFF[k]) l = k;
    int j = i - OFF[l];
    int Co = CoA[l], Ci = CiA[l];
    int o = j % Co;
    int cij = j / Co;
    int c = cij / 9, ij = cij % 9;
    wt[i] = wp.p[l][((size_t)o * Ci + c) * 9 + ij];
}

// ─── stride-1, wide images (W>=32): 32x16 tile, 2 px/thread, 8 outs ───
template<int CB>
__global__ void __launch_bounds__(256) conv_s1(
    const float* __restrict__ in, const float* __restrict__ wt,
    const float* __restrict__ bias, const float* __restrict__ kern,
    float* __restrict__ out, int Ci, int Co, int H, int W, int tilesX)
{
    constexpr int ROWS = 18, PITCH = 40, CSZ = ROWS * PITCH;   // 720
    constexpr int ISLOTS = CB * ROWS * 10;
    constexpr int NIT = (ISLOTS + 255) / 256;
    __shared__ __align__(16) float s_in[2][CB * CSZ];
    __shared__ __align__(16) float s_w[2][CB * 72];   // [c][ij][8]

    const int tid = threadIdx.x;
    const int lx = tid % 16, ty = tid / 16;            // col-pair, row in tile
    const int tX = blockIdx.x % tilesX, tY = blockIdx.x / tilesX;
    const int ocg = blockIdx.y, b = blockIdx.z;
    const int oh = tY * 16 + ty, ow0 = tX * 32 + 2 * lx;
    const size_t HW = (size_t)H * W;

    // Per-pixel PAC values for both pixels (constant across channel loop)
    float k0[9], k1[9];
    if (kern) {
        const float* kp = kern + (size_t)b * 9 * HW + (size_t)oh * W + ow0;
        #pragma unroll
        for (int t = 0; t < 9; t++) {
            float2 kk = *(const float2*)(kp + (size_t)t * HW);
            k0[t] = kk.x; k1[t] = kk.y;
        }
    } else {
        #pragma unroll
        for (int t = 0; t < 9; t++) { k0[t] = 1.0f; k1[t] = 1.0f; }
    }

    u64 acc[8];   // [px][outpair]: acc[px*4+q] -> outputs (2q,2q+1) of pixel px
    #pragma unroll
    for (int p = 0; p < 8; p++) acc[p] = 0ull;

    for (int i = tid; i < 2 * CB * CSZ; i += 256) (&s_in[0][0])[i] = 0.0f;
    __syncthreads();

    const uint32_t sinA[2] = {(uint32_t)__cvta_generic_to_shared(&s_in[0][0]),
                              (uint32_t)__cvta_generic_to_shared(&s_in[1][0])};
    const uint32_t swA[2]  = {(uint32_t)__cvta_generic_to_shared(&s_w[0][0]),
                              (uint32_t)__cvta_generic_to_shared(&s_w[1][0])};
    const int NG = Ci / CB;
    const int gr0 = tY * 16 - 1;
    const int gc0 = tX * 32 - 4;

    // Hoisted staging descriptors
    const float* gsrc[NIT];
    uint32_t soff[NIT];
    bool sval[NIT];
    {
        const float* ib0 = in + (size_t)b * Ci * HW;
        #pragma unroll
        for (int k = 0; k < NIT; k++) {
            int slot = tid + k * 256;
            int c = slot / 180, rem = slot % 180;
            int r = rem / 10, q = rem % 10;
            int gr = gr0 + r, gc = gc0 + 4 * q;
            sval[k] = (slot < ISLOTS) && ((unsigned)gr < (unsigned)H) &&
                      (gc >= 0) && (gc + 4 <= W);
            soff[k] = (uint32_t)(c * CSZ + r * PITCH + 4 * q) * 4u;
            gsrc[k] = ib0 + (size_t)c * HW + (size_t)gr * W + gc;
        }
    }
    const bool wval = tid < CB * 18;
    uint32_t woff = 0;
    const float* wsrc = wt;
    {
        int c = tid / 18, rem = tid % 18, ij = rem / 2, q = rem % 2;
        woff = (uint32_t)(c * 72 + ij * 8 + 4 * q) * 4u;
        wsrc = wt + ((size_t)c * 9 + ij) * Co + (size_t)ocg * 8 + 4 * q;
    }
    const size_t gstep = (size_t)CB * HW;
    const size_t wstep = (size_t)CB * 9 * Co;

    auto stage = [&](int buf) {
        #pragma unroll
        for (int k = 0; k < NIT; k++) {
            if (sval[k]) cp_async16(sinA[buf] + soff[k], gsrc[k]);
            gsrc[k] += gstep;
        }
        if (wval) { cp_async16(swA[buf] + woff, wsrc); }
        wsrc += wstep;
    };

    stage(0);
    CP_COMMIT();

    const int base_off = ty * PITCH + 2 * lx + 3;   // col of px0's left tap

    for (int cg = 0; cg < NG; cg++) {
        CP_WAIT0();
        __syncthreads();
        if (cg + 1 < NG) { stage((cg + 1) & 1); CP_COMMIT(); }
        const int buf = cg & 1;

        #pragma unroll
        for (int c = 0; c < CB; c++) {
            const float* sp = &s_in[buf][c * CSZ + base_off];
            const ulonglong2* wp = reinterpret_cast<const ulonglong2*>(&s_w[buf][c * 72]);
            #pragma unroll
            for (int i = 0; i < 3; i++) {
                const float* rp = sp + i * PITCH;
                float xl = rp[0];
                float2 xm = *(const float2*)(rp + 1);
                float xr = rp[3];
                float x[4] = {xl, xm.x, xm.y, xr};
                #pragma unroll
                for (int j = 0; j < 3; j++) {
                    const int t = 3 * i + j;
                    float v0 = x[j]     * k0[t];
                    float v1 = x[j + 1] * k1[t];
                    u64 vv0, vv1;
                    PACK2(vv0, v0, v0);
                    PACK2(vv1, v1, v1);
                    ulonglong2 wa = wp[2 * t];
                    ulonglong2 wb = wp[2 * t + 1];
                    FFMA2(acc[0], wa.x, vv0); FFMA2(acc[1], wa.y, vv0);
                    FFMA2(acc[2], wb.x, vv0); FFMA2(acc[3], wb.y, vv0);
                    FFMA2(acc[4], wa.x, vv1); FFMA2(acc[5], wa.y, vv1);
                    FFMA2(acc[6], wb.x, vv1); FFMA2(acc[7], wb.y, vv1);
                }
            }
        }
    }

    #pragma unroll
    for (int q = 0; q < 4; q++) {
        int o0 = ocg * 8 + 2 * q;
        float a0, a1, b0v, b1v;
        UNPACK2(a0, a1, acc[q]);       // px0: outputs o0, o0+1
        UNPACK2(b0v, b1v, acc[4 + q]); // px1: outputs o0, o0+1
        float bias0 = bias[o0], bias1 = bias[o0 + 1];
        float p00 = a0 + bias0, p01 = b0v + bias0;
        float p10 = a1 + bias1, p11 = b1v + bias1;
        p00 = p00 > 0.0f ? p00 : 0.0f;
        p01 = p01 > 0.0f ? p01 : 0.0f;
        p10 = p10 > 0.0f ? p10 : 0.0f;
        p11 = p11 > 0.0f ? p11 : 0.0f;
        *(float2*)&out[((size_t)(b * Co + o0)     * H + oh) * W + ow0] = make_float2(p00, p01);
        *(float2*)&out[((size_t)(b * Co + o0 + 1) * H + oh) * W + ow0] = make_float2(p10, p11);
    }
}

// ─── stride-1, 16x16 images: whole image per block, PITCH=48, CB=4 ───
__global__ void __launch_bounds__(256) conv_s1_16(
    const float* __restrict__ in, const float* __restrict__ wt,
    const float* __restrict__ bias, const float* __restrict__ kern,
    float* __restrict__ out, int Ci, int Co)
{
    constexpr int CB = 4, ROWS = 18, PITCH = 48, CSZ = ROWS * PITCH;
    constexpr int ISLOTS = CB * ROWS * 6;
    constexpr int NIT = 2;
    __shared__ __align__(16) float s_in[2][CB * CSZ];
    __shared__ __align__(16) float s_w[2][CB * 72];

    const int tid = threadIdx.x;
    const int tx = tid % 16, ty = tid / 16;
    const int ocg = blockIdx.y, b = blockIdx.z;
    const size_t HW = 256;

    float kreg[9];
    {
        const float* kp = kern + (size_t)b * 9 * HW + (size_t)ty * 16 + tx;
        #pragma unroll
        for (int t = 0; t < 9; t++) kreg[t] = kp[(size_t)t * HW];
    }

    u64 acc[4];
    #pragma unroll
    for (int p = 0; p < 4; p++) acc[p] = 0ull;

    for (int i = tid; i < 2 * CB * CSZ; i += 256) (&s_in[0][0])[i] = 0.0f;
    __syncthreads();

    const uint32_t sinA[2] = {(uint32_t)__cvta_generic_to_shared(&s_in[0][0]),
                              (uint32_t)__cvta_generic_to_shared(&s_in[1][0])};
    const uint32_t swA[2]  = {(uint32_t)__cvta_generic_to_shared(&s_w[0][0]),
                              (uint32_t)__cvta_generic_to_shared(&s_w[1][0])};
    const int NG = Ci / CB;

    const float* gsrc[NIT];
    uint32_t soff[NIT];
    bool sval[NIT];
    {
        const float* ib0 = in + (size_t)b * Ci * HW;
        #pragma unroll
        for (int k = 0; k < NIT; k++) {
            int slot = tid + k * 256;
            int c = slot / 108, rem = slot % 108;
            int r = rem / 6, q = rem % 6;
            int gr = r - 1, gc = 4 * q - 4;
            sval[k] = (slot < ISLOTS) && ((unsigned)gr < 16u) && (gc >= 0) && (gc + 4 <= 16);
            soff[k] = (uint32_t)(c * CSZ + r * PITCH + 4 * q) * 4u;
            gsrc[k] = ib0 + (size_t)c * HW + (size_t)gr * 16 + gc;
        }
    }
    const bool wval = tid < CB * 18;
    uint32_t woff = 0;
    const float* wsrc = wt;
    {
        int c = tid / 18, rem = tid % 18, ij = rem / 2, q = rem % 2;
        woff = (uint32_t)(c * 72 + ij * 8 + 4 * q) * 4u;
        wsrc = wt + ((size_t)c * 9 + ij) * Co + (size_t)ocg * 8 + 4 * q;
    }
    const size_t gstep = (size_t)CB * HW;
    const size_t wstep = (size_t)CB * 9 * Co;

    auto stage = [&](int buf) {
        #pragma unroll
        for (int k = 0; k < NIT; k++) {
            if (sval[k]) cp_async16(sinA[buf] + soff[k], gsrc[k]);
            gsrc[k] += gstep;
        }
        if (wval) { cp_async16(swA[buf] + woff, wsrc); }
        wsrc += wstep;
    };

    stage(0);
    CP_COMMIT();

    const int base_off = ty * PITCH + tx + 3;

    for (int cg = 0; cg < NG; cg++) {
        CP_WAIT0();
        __syncthreads();
        if (cg + 1 < NG) { stage((cg + 1) & 1); CP_COMMIT(); }
        const int buf = cg & 1;

        #pragma unroll
        for (int c = 0; c < CB; c++) {
            const float* sp = &s_in[buf][c * CSZ + base_off];
            const ulonglong2* wp = reinterpret_cast<const ulonglong2*>(&s_w[buf][c * 72]);
            #pragma unroll
            for (int t = 0; t < 9; t++) {
                float v = sp[(t / 3) * PITCH + (t % 3)] * kreg[t];
                u64 vv;
                PACK2(vv, v, v);
                ulonglong2 wa = wp[2 * t];
                ulonglong2 wbv = wp[2 * t + 1];
                FFMA2(acc[0], wa.x,  vv); FFMA2(acc[1], wa.y,  vv);
                FFMA2(acc[2], wbv.x, vv); FFMA2(acc[3], wbv.y, vv);
            }
        }
    }

    #pragma unroll
    for (int p = 0; p < 4; p++) {
        int o = ocg * 8 + 2 * p;
        float lo, hi;
        UNPACK2(lo, hi, acc[p]);
        float v0 = lo + bias[o], v1 = hi + bias[o + 1];
        v0 = v0 > 0.0f ? v0 : 0.0f;
        v1 = v1 > 0.0f ? v1 : 0.0f;
        out[((size_t)(b * Co + o)     * 16 + ty) * 16 + tx] = v0;
        out[((size_t)(b * Co + o + 1) * 16 + ty) * 16 + tx] = v1;
    }
}

// ─── stride-2: 16x16 output tile, 1 px/thread, 8 outputs, CB=2 ───
__global__ void __launch_bounds__(256) conv_s2(
    const float* __restrict__ in, const float* __restrict__ wt,
    const float* __restrict__ bias, const float* __restrict__ kern,
    float* __restrict__ out, int Ci, int Co, int H, int W, int tilesX)
{
    constexpr int CB = 2, ROWS = 33, PITCH = 40, CSZ = ROWS * PITCH;
    constexpr int ISLOTS = CB * ROWS * 10;
    constexpr int NIT = 3;
    __shared__ __align__(16) float s_in[2][CB * CSZ];
    __shared__ __align__(16) float s_w[2][CB * 72];

    const int tid = threadIdx.x;
    const int tx = tid % 16, ty = tid / 16;
    const int tX = blockIdx.x % tilesX, tY = blockIdx.x / tilesX;
    const int ocg = blockIdx.y, b = blockIdx.z;
    const int Hout = H / 2, Wout = W / 2;
    const int oh = tY * 16 + ty, ow = tX * 16 + tx;
    const size_t HW = (size_t)H * W;

    float kreg[9];
    if (kern) {
        const float* kp = kern + (size_t)b * 9 * HW + (size_t)(oh * 2) * W + ow * 2;
        #pragma unroll
        for (int t = 0; t < 9; t++) kreg[t] = kp[(size_t)t * HW];
    } else {
        #pragma unroll
        for (int t = 0; t < 9; t++) kreg[t] = 1.0f;
    }

    u64 acc[4];
    #pragma unroll
    for (int p = 0; p < 4; p++) acc[p] = 0ull;

    for (int i = tid; i < 2 * CB * CSZ; i += 256) (&s_in[0][0])[i] = 0.0f;
    __syncthreads();

    const uint32_t sinA[2] = {(uint32_t)__cvta_generic_to_shared(&s_in[0][0]),
                              (uint32_t)__cvta_generic_to_shared(&s_in[1][0])};
    const uint32_t swA[2]  = {(uint32_t)__cvta_generic_to_shared(&s_w[0][0]),
                              (uint32_t)__cvta_generic_to_shared(&s_w[1][0])};
    const int NG = Ci / CB;
    const int gr0 = tY * 32 - 1;
    const int gc0 = tX * 32 - 4;

    const float* gsrc[NIT];
    uint32_t soff[NIT];
    bool sval[NIT];
    {
        const float* ib0 = in + (size_t)b * Ci * HW;
        #pragma unroll
        for (int k = 0; k < NIT; k++) {
            int slot = tid + k * 256;
            int c = slot / 330, rem = slot % 330;
            int r = rem / 10, q = rem % 10;
            int gr = gr0 + r, gc = gc0 + 4 * q;
            sval[k] = (slot < ISLOTS) && ((unsigned)gr < (unsigned)H) &&
                      (gc >= 0) && (gc + 4 <= W);
            soff[k] = (uint32_t)(c * CSZ + r * PITCH + 4 * q) * 4u;
            gsrc[k] = ib0 + (size_t)c * HW + (size_t)gr * W + gc;
        }
    }
    const bool wval = tid < CB * 18;
    uint32_t woff = 0;
    const float* wsrc = wt;
    {
        int c = tid / 18, rem = tid % 18, ij = rem / 2, q = rem % 2;
        woff = (uint32_t)(c * 72 + ij * 8 + 4 * q) * 4u;
        wsrc = wt + ((size_t)c * 9 + ij) * Co + (size_t)ocg * 8 + 4 * q;
    }
    const size_t gstep = (size_t)CB * HW;
    const size_t wstep = (size_t)CB * 9 * Co;

    auto stage = [&](int buf) {
        #pragma unroll
        for (int k = 0; k < NIT; k++) {
            if (sval[k]) cp_async16(sinA[buf] + soff[k], gsrc[k]);
            gsrc[k] += gstep;
        }
        if (wval) { cp_async16(swA[buf] + woff, wsrc); }
        wsrc += wstep;
    };

    stage(0);
    CP_COMMIT();

    const int base_off = (2 * ty) * PITCH + 2 * tx + 3;

    for (int cg = 0; cg < NG; cg++) {
        CP_WAIT0();
        __syncthreads();
        if (cg + 1 < NG) { stage((cg + 1) & 1); CP_COMMIT(); }
        const int buf = cg & 1;

        #pragma unroll
        for (int c = 0; c < CB; c++) {
            const float* sp = &s_in[buf][c * CSZ + base_off];
            const ulonglong2* wp = reinterpret_cast<const ulonglong2*>(&s_w[buf][c * 72]);
            #pragma unroll
            for (int t = 0; t < 9; t++) {
                float v = sp[(t / 3) * PITCH + (t % 3)] * kreg[t];
                u64 vv;
                PACK2(vv, v, v);
                ulonglong2 wa = wp[2 * t];
                ulonglong2 wbv = wp[2 * t + 1];
                FFMA2(acc[0], wa.x,  vv); FFMA2(acc[1], wa.y,  vv);
                FFMA2(acc[2], wbv.x, vv); FFMA2(acc[3], wbv.y, vv);
            }
        }
    }

    #pragma unroll
    for (int p = 0; p < 4; p++) {
        int o = ocg * 8 + 2 * p;
        float lo, hi;
        UNPACK2(lo, hi, acc[p]);
        float v0 = lo + bias[o], v1 = hi + bias[o + 1];
        v0 = v0 > 0.0f ? v0 : 0.0f;
        v1 = v1 > 0.0f ? v1 : 0.0f;
        out[((size_t)(b * Co + o)     * Hout + oh) * Wout + ow] = v0;
        out[((size_t)(b * Co + o + 1) * Hout + oh) * Wout + ow] = v1;
    }
}

__global__ void pac_gauss_kernel(const float* __restrict__ f, float* __restrict__ out,
                                 int C, int H, int W, float coeff2)
{
    const int b = blockIdx.z;
    const int idx = blockIdx.x * blockDim.x + threadIdx.x;
    if (idx >= H * W) return;
    const int h = idx / W, w = idx % W;

    float acc[9];
    #pragma unroll
    for (int t = 0; t < 9; t++) acc[t] = 0.0f;

    const float* fb = f + (size_t)b * C * H * W;
    for (int c = 0; c < C; c++) {
        const float* fc = fb + (size_t)c * H * W;
        float ctr = fc[idx];
        #pragma unroll
        for (int i = 0; i < 3; i++)
        #pragma unroll
        for (int j = 0; j < 3; j++) {
            int hh = h + i - 1, ww = w + j - 1;
            float nb = (hh >= 0 && hh < H && ww >= 0 && ww < W) ? fc[hh * W + ww] : 0.0f;
            float d = nb - ctr;
            acc[i * 3 + j] += d * d;
        }
    }

    float* ob = out + (size_t)b * 9 * H * W;
    #pragma unroll
    for (int t = 0; t < 9; t++)
        ob[(size_t)t * H * W + idx] = expf(-0.5f * coeff2 * acc[t]);
}

// ─── host side ───

static void conv_s1_l(const float* in, const float* wt, const float* b, const float* kern,
                      float* out, int Ci, int Co, int H, int W)
{
    if (W >= 32) {
        int tilesX = W / 32;
        dim3 grid(tilesX * (H / 16), Co / 8, 2);
        if (Ci % 4 == 0)
            conv_s1<4><<<grid, 256>>>(in, wt, b, kern, out, Ci, Co, H, W, tilesX);
        else
            conv_s1<1><<<grid, 256>>>(in, wt, b, kern, out, Ci, Co, H, W, tilesX);
    } else {
        dim3 grid(1, Co / 8, 2);
        conv_s1_16<<<grid, 256>>>(in, wt, b, kern, out, Ci, Co);
    }
}

static void conv_s2_l(const float* in, const float* wt, const float* b, const float* kern,
                      float* out, int Ci, int Co, int H, int W)
{
    int tilesX = W / 32;
    dim3 grid(tilesX * (H / 32), Co / 8, 2);
    conv_s2<<<grid, 256>>>(in, wt, b, kern, out, Ci, Co, H, W, tilesX);
}

static void pac_layer(const float* f, float* out, int C, int H, int W, float coeff2)
{
    int hw = H * W;
    dim3 grid((hw + 255) / 256, 1, 2);
    pac_gauss_kernel<<<grid, 256>>>(f, out, C, H, W, coeff2);
}

extern "C" void kernel_launch(void* const* d_in, const int* in_sizes, int n_in,
                              void* d_out, int out_size)
{
    const float* x = (const float*)d_in[0];
    WPtrs wp;
    const float* B14[14];
    for (int i = 0; i < 14; i++) {
        wp.p[i] = (const float*)d_in[1 + 2 * i];
        B14[i]  = (const float*)d_in[2 + 2 * i];
    }

    float* bufA; float* bufB; float* wT;
    cudaGetSymbolAddress((void**)&bufA, g_bufA);
    cudaGetSymbolAddress((void**)&bufB, g_bufB);
    cudaGetSymbolAddress((void**)&wT,  g_wT);

    static const size_t OFF[15] = {0,576,37440,74304,148032,295488,442944,737856,1327680,
                                   1917504,3097152,5456448,7815744,12534336,21971520};
    const float* wt[14];
    for (int l = 0; l < 14; l++) wt[l] = wT + OFF[l];

    transpose_all_kernel<<<(21971520 + 255) / 256, 256>>>(wp, wT);

    float* out = (float*)d_out;
    float* h1 = out;
    float* h2 = h1 + 8388608;
    float* h3 = h2 + 4194304;
    float* h4 = h3 + 2097152;
    float* h5 = h4 + 1048576;
    float* k2 = h5 + 524288;
    float* k3 = k2 + 294912;
    float* k4 = k3 + 73728;
    float* k5 = k4 + 18432;

    const float KC2 = 1e-4f * 1e-4f;

    // Stage 1
    conv_s1_l(x,    wt[0], B14[0], nullptr, bufA, 1,  64, 256, 256);
    conv_s1_l(bufA, wt[1], B14[1], nullptr, h1,   64, 64, 256, 256);
    conv_s2_l(h1,   wt[2], B14[2], nullptr, bufA, 64, 64, 256, 256);   // -> 2,64,128,128

    // Stage 2
    pac_layer(bufA, k2, 64, 128, 128, KC2);
    conv_s1_l(bufA, wt[3], B14[3], k2, bufB, 64,  128, 128, 128);
    conv_s1_l(bufB, wt[4], B14[4], k2, h2,   128, 128, 128, 128);
    conv_s2_l(h2,   wt[5], B14[5], k2, bufA, 128, 128, 128, 128);      // -> 2,128,64,64

    // Stage 3
    pac_layer(bufA, k3, 128, 64, 64, KC2);
    conv_s1_l(bufA, wt[6], B14[6], k3, bufB, 128, 256, 64, 64);
    conv_s1_l(bufB, wt[7], B14[7], k3, h3,   256, 256, 64, 64);
    conv_s2_l(h3,   wt[8], B14[8], k3, bufA, 256, 256, 64, 64);        // -> 2,256,32,32

    // Stage 4 (guidance h4*2 -> coeff^2 = 4)
    pac_layer(bufA, k4, 256, 32, 32, 4.0f);
    conv_s1_l(bufA, wt[9],  B14[9],  k4, bufB, 256, 512, 32, 32);
    conv_s1_l(bufB, wt[10], B14[10], k4, h4,   512, 512, 32, 32);
    conv_s2_l(h4,   wt[11], B14[11], k4, bufA, 512, 512, 32, 32);      // -> 2,512,16,16

    // Stage 5
    pac_layer(bufA, k5, 512, 16, 16, KC2);
    conv_s1_l(bufA, wt[12], B14[12], k5, bufB, 512,  1024, 16, 16);
    conv_s1_l(bufB, wt[13], B14[13], k5, h5,   1024, 1024, 16, 16);
}

// round 8
// speedup vs baseline: 1.2489x; 1.0618x over previous
#include <cuda_runtime.h>
#include <cstdint>

typedef unsigned long long u64;

__device__ float g_bufA[8388608];
__device__ float g_bufB[4194304];
__device__ float g_wT [21971520];   // transposed weights [c][ij][o], all 14 layers packed

__device__ __forceinline__ void cp_async16(uint32_t saddr, const float* gptr) {
    asm volatile("cp.async.cg.shared.global [%0], [%1], 16;" :: "r"(saddr), "l"(gptr));
}
#define CP_COMMIT() asm volatile("cp.async.commit_group;" ::: "memory")
#define CP_WAIT0()  asm volatile("cp.async.wait_group 0;" ::: "memory")
#define FFMA2(acc, w, v) asm("fma.rn.f32x2 %0, %1, %2, %0;" : "+l"(acc) : "l"(w), "l"(v))
#define PACK2(d, a, b)   asm("mov.b64 %0, {%1, %2};" : "=l"(d) : "f"(a), "f"(b))
#define UNPACK2(lo, hi, p) asm("mov.b64 {%0, %1}, %2;" : "=f"(lo), "=f"(hi) : "l"(p))

// ─── fused weight transpose: one launch for all 14 layers ───
struct WPtrs { const float* p[14]; };

__global__ void transpose_all_kernel(WPtrs wp, float* __restrict__ wt)
{
    const int i = blockIdx.x * 256 + threadIdx.x;
    if (i >= 21971520) return;
    const int CiA[14] = {1,64,64, 64,128,128, 128,256,256, 256,512,512, 512,1024};
    const int CoA[14] = {64,64,64, 128,128,128, 256,256,256, 512,512,512, 1024,1024};
    const int OFF[15] = {0,576,37440,74304,148032,295488,442944,737856,1327680,
                         1917504,3097152,5456448,7815744,12534336,21971520};
    int l = 0;
    #pragma unroll
    for (int k = 1; k < 14; k++) if (i >= OFF[k]) l = k;
    int j = i - OFF[l];
    int Co = CoA[l], Ci = CiA[l];
    int o = j % Co;
    int cij = j / Co;
    int c = cij / 9, ij = cij % 9;
    wt[i] = wp.p[l][((size_t)o * Ci + c) * 9 + ij];
}

// Common weight-tap FMA: 16 outputs (8 packed pairs) for one tap value vv.
#define TAP16(wq, t, vv, A)                                            \
    {                                                                  \
        ulonglong2 w0 = (wq)[4*(t)], w1 = (wq)[4*(t)+1],               \
                   w2 = (wq)[4*(t)+2], w3 = (wq)[4*(t)+3];             \
        FFMA2((A)[0], w0.x, vv); FFMA2((A)[1], w0.y, vv);              \
        FFMA2((A)[2], w1.x, vv); FFMA2((A)[3], w1.y, vv);              \
        FFMA2((A)[4], w2.x, vv); FFMA2((A)[5], w2.y, vv);              \
        FFMA2((A)[6], w3.x, vv); FFMA2((A)[7], w3.y, vv);              \
    }

// ─── stride-1, wide images (W>=32): 32x16 tile, 2 px/thread, 16 outs ───
template<int CB>
__global__ void __launch_bounds__(256) conv_s1(
    const float* __restrict__ in, const float* __restrict__ wt,
    const float* __restrict__ bias, const float* __restrict__ kern,
    float* __restrict__ out, int Ci, int Co, int H, int W, int tilesX)
{
    constexpr int ROWS = 18, PITCH = 40, CSZ = ROWS * PITCH;   // 720
    constexpr int ISLOTS = CB * ROWS * 10;
    constexpr int NIT = (ISLOTS + 255) / 256;
    __shared__ __align__(16) float s_in[2][CB * CSZ];
    __shared__ __align__(16) float s_w[2][CB * 144];   // [c][ij][16]

    const int tid = threadIdx.x;
    const int lx = tid % 16, ty = tid / 16;
    const int tX = blockIdx.x % tilesX, tY = blockIdx.x / tilesX;
    const int ocg = blockIdx.y, b = blockIdx.z;
    const int oh = tY * 16 + ty, ow0 = tX * 32 + 2 * lx;
    const size_t HW = (size_t)H * W;

    float k0[9], k1[9];
    if (kern) {
        const float* kp = kern + (size_t)b * 9 * HW + (size_t)oh * W + ow0;
        #pragma unroll
        for (int t = 0; t < 9; t++) {
            float2 kk = *(const float2*)(kp + (size_t)t * HW);
            k0[t] = kk.x; k1[t] = kk.y;
        }
    } else {
        #pragma unroll
        for (int t = 0; t < 9; t++) { k0[t] = 1.0f; k1[t] = 1.0f; }
    }

    u64 accA[8], accB[8];   // px0 / px1, 8 output pairs each
    #pragma unroll
    for (int p = 0; p < 8; p++) { accA[p] = 0ull; accB[p] = 0ull; }

    for (int i = tid; i < 2 * CB * CSZ; i += 256) (&s_in[0][0])[i] = 0.0f;
    __syncthreads();

    const uint32_t sinA[2] = {(uint32_t)__cvta_generic_to_shared(&s_in[0][0]),
                              (uint32_t)__cvta_generic_to_shared(&s_in[1][0])};
    const uint32_t swA[2]  = {(uint32_t)__cvta_generic_to_shared(&s_w[0][0]),
                              (uint32_t)__cvta_generic_to_shared(&s_w[1][0])};
    const int NG = Ci / CB;
    const int gr0 = tY * 16 - 1;
    const int gc0 = tX * 32 - 4;

    const float* gsrc[NIT];
    uint32_t soff[NIT];
    bool sval[NIT];
    {
        const float* ib0 = in + (size_t)b * Ci * HW;
        #pragma unroll
        for (int k = 0; k < NIT; k++) {
            int slot = tid + k * 256;
            int c = slot / 180, rem = slot % 180;
            int r = rem / 10, q = rem % 10;
            int gr = gr0 + r, gc = gc0 + 4 * q;
            sval[k] = (slot < ISLOTS) && ((unsigned)gr < (unsigned)H) &&
                      (gc >= 0) && (gc + 4 <= W);
            soff[k] = (uint32_t)(c * CSZ + r * PITCH + 4 * q) * 4u;
            gsrc[k] = ib0 + (size_t)c * HW + (size_t)gr * W + gc;
        }
    }
    const bool wval = tid < CB * 36;
    uint32_t woff = 0;
    const float* wsrc = wt;
    {
        int c = tid / 36, rem = tid % 36, ij = rem / 4, q = rem % 4;
        woff = (uint32_t)(c * 144 + ij * 16 + 4 * q) * 4u;
        wsrc = wt + ((size_t)c * 9 + ij) * Co + (size_t)ocg * 16 + 4 * q;
    }
    const size_t gstep = (size_t)CB * HW;
    const size_t wstep = (size_t)CB * 9 * Co;

    auto stage = [&](int buf) {
        #pragma unroll
        for (int k = 0; k < NIT; k++) {
            if (sval[k]) cp_async16(sinA[buf] + soff[k], gsrc[k]);
            gsrc[k] += gstep;
        }
        if (wval) { cp_async16(swA[buf] + woff, wsrc); }
        wsrc += wstep;
    };

    stage(0);
    CP_COMMIT();

    const int base_off = ty * PITCH + 2 * lx + 3;

    for (int cg = 0; cg < NG; cg++) {
        CP_WAIT0();
        __syncthreads();
        if (cg + 1 < NG) { stage((cg + 1) & 1); CP_COMMIT(); }
        const int buf = cg & 1;

        #pragma unroll
        for (int c = 0; c < CB; c++) {
            const float* sp = &s_in[buf][c * CSZ + base_off];
            const ulonglong2* wq = reinterpret_cast<const ulonglong2*>(&s_w[buf][c * 144]);
            #pragma unroll
            for (int i = 0; i < 3; i++) {
                const float* rp = sp + i * PITCH;
                float xl = rp[0];
                float2 xm = *(const float2*)(rp + 1);
                float xr = rp[3];
                float x[4] = {xl, xm.x, xm.y, xr};
                #pragma unroll
                for (int j = 0; j < 3; j++) {
                    const int t = 3 * i + j;
                    float v0 = x[j]     * k0[t];
                    float v1 = x[j + 1] * k1[t];
                    u64 vv0, vv1;
                    PACK2(vv0, v0, v0);
                    PACK2(vv1, v1, v1);
                    TAP16(wq, t, vv0, accA);
                    TAP16(wq, t, vv1, accB);
                }
            }
        }
    }

    #pragma unroll
    for (int q = 0; q < 8; q++) {
        int o0 = ocg * 16 + 2 * q;
        float a0, a1, b0v, b1v;
        UNPACK2(a0, a1, accA[q]);
        UNPACK2(b0v, b1v, accB[q]);
        float bias0 = bias[o0], bias1 = bias[o0 + 1];
        float p00 = a0 + bias0, p01 = b0v + bias0;
        float p10 = a1 + bias1, p11 = b1v + bias1;
        p00 = p00 > 0.0f ? p00 : 0.0f;
        p01 = p01 > 0.0f ? p01 : 0.0f;
        p10 = p10 > 0.0f ? p10 : 0.0f;
        p11 = p11 > 0.0f ? p11 : 0.0f;
        *(float2*)&out[((size_t)(b * Co + o0)     * H + oh) * W + ow0] = make_float2(p00, p01);
        *(float2*)&out[((size_t)(b * Co + o0 + 1) * H + oh) * W + ow0] = make_float2(p10, p11);
    }
}

// ─── stride-1, 16x16 images: whole image per block, 1 px/thread, 16 outs ───
__global__ void __launch_bounds__(256) conv_s1_16(
    const float* __restrict__ in, const float* __restrict__ wt,
    const float* __restrict__ bias, const float* __restrict__ kern,
    float* __restrict__ out, int Ci, int Co)
{
    constexpr int CB = 4, ROWS = 18, PITCH = 48, CSZ = ROWS * PITCH;
    constexpr int ISLOTS = CB * ROWS * 6;
    constexpr int NIT = 2;
    __shared__ __align__(16) float s_in[2][CB * CSZ];
    __shared__ __align__(16) float s_w[2][CB * 144];

    const int tid = threadIdx.x;
    const int tx = tid % 16, ty = tid / 16;
    const int ocg = blockIdx.y, b = blockIdx.z;
    const size_t HW = 256;

    float kreg[9];
    {
        const float* kp = kern + (size_t)b * 9 * HW + (size_t)ty * 16 + tx;
        #pragma unroll
        for (int t = 0; t < 9; t++) kreg[t] = kp[(size_t)t * HW];
    }

    u64 acc[8];
    #pragma unroll
    for (int p = 0; p < 8; p++) acc[p] = 0ull;

    for (int i = tid; i < 2 * CB * CSZ; i += 256) (&s_in[0][0])[i] = 0.0f;
    __syncthreads();

    const uint32_t sinA[2] = {(uint32_t)__cvta_generic_to_shared(&s_in[0][0]),
                              (uint32_t)__cvta_generic_to_shared(&s_in[1][0])};
    const uint32_t swA[2]  = {(uint32_t)__cvta_generic_to_shared(&s_w[0][0]),
                              (uint32_t)__cvta_generic_to_shared(&s_w[1][0])};
    const int NG = Ci / CB;

    const float* gsrc[NIT];
    uint32_t soff[NIT];
    bool sval[NIT];
    {
        const float* ib0 = in + (size_t)b * Ci * HW;
        #pragma unroll
        for (int k = 0; k < NIT; k++) {
            int slot = tid + k * 256;
            int c = slot / 108, rem = slot % 108;
            int r = rem / 6, q = rem % 6;
            int gr = r - 1, gc = 4 * q - 4;
            sval[k] = (slot < ISLOTS) && ((unsigned)gr < 16u) && (gc >= 0) && (gc + 4 <= 16);
            soff[k] = (uint32_t)(c * CSZ + r * PITCH + 4 * q) * 4u;
            gsrc[k] = ib0 + (size_t)c * HW + (size_t)gr * 16 + gc;
        }
    }
    const bool wval = tid < CB * 36;
    uint32_t woff = 0;
    const float* wsrc = wt;
    {
        int c = tid / 36, rem = tid % 36, ij = rem / 4, q = rem % 4;
        woff = (uint32_t)(c * 144 + ij * 16 + 4 * q) * 4u;
        wsrc = wt + ((size_t)c * 9 + ij) * Co + (size_t)ocg * 16 + 4 * q;
    }
    const size_t gstep = (size_t)CB * HW;
    const size_t wstep = (size_t)CB * 9 * Co;

    auto stage = [&](int buf) {
        #pragma unroll
        for (int k = 0; k < NIT; k++) {
            if (sval[k]) cp_async16(sinA[buf] + soff[k], gsrc[k]);
            gsrc[k] += gstep;
        }
        if (wval) { cp_async16(swA[buf] + woff, wsrc); }
        wsrc += wstep;
    };

    stage(0);
    CP_COMMIT();

    const int base_off = ty * PITCH + tx + 3;

    for (int cg = 0; cg < NG; cg++) {
        CP_WAIT0();
        __syncthreads();
        if (cg + 1 < NG) { stage((cg + 1) & 1); CP_COMMIT(); }
        const int buf = cg & 1;

        #pragma unroll
        for (int c = 0; c < CB; c++) {
            const float* sp = &s_in[buf][c * CSZ + base_off];
            const ulonglong2* wq = reinterpret_cast<const ulonglong2*>(&s_w[buf][c * 144]);
            #pragma unroll
            for (int t = 0; t < 9; t++) {
                float v = sp[(t / 3) * PITCH + (t % 3)] * kreg[t];
                u64 vv;
                PACK2(vv, v, v);
                TAP16(wq, t, vv, acc);
            }
        }
    }

    #pragma unroll
    for (int p = 0; p < 8; p++) {
        int o = ocg * 16 + 2 * p;
        float lo, hi;
        UNPACK2(lo, hi, acc[p]);
        float v0 = lo + bias[o], v1 = hi + bias[o + 1];
        v0 = v0 > 0.0f ? v0 : 0.0f;
        v1 = v1 > 0.0f ? v1 : 0.0f;
        out[((size_t)(b * Co + o)     * 16 + ty) * 16 + tx] = v0;
        out[((size_t)(b * Co + o + 1) * 16 + ty) * 16 + tx] = v1;
    }
}

// ─── stride-2: 16x16 output tile, 1 px/thread, 16 outputs, CB=2 ───
__global__ void __launch_bounds__(256) conv_s2(
    const float* __restrict__ in, const float* __restrict__ wt,
    const float* __restrict__ bias, const float* __restrict__ kern,
    float* __restrict__ out, int Ci, int Co, int H, int W, int tilesX)
{
    constexpr int CB = 2, ROWS = 33, PITCH = 40, CSZ = ROWS * PITCH;
    constexpr int ISLOTS = CB * ROWS * 10;
    constexpr int NIT = 3;
    __shared__ __align__(16) float s_in[2][CB * CSZ];
    __shared__ __align__(16) float s_w[2][CB * 144];

    const int tid = threadIdx.x;
    const int tx = tid % 16, ty = tid / 16;
    const int tX = blockIdx.x % tilesX, tY = blockIdx.x / tilesX;
    const int ocg = blockIdx.y, b = blockIdx.z;
    const int Hout = H / 2, Wout = W / 2;
    const int oh = tY * 16 + ty, ow = tX * 16 + tx;
    const size_t HW = (size_t)H * W;

    float kreg[9];
    if (kern) {
        const float* kp = kern + (size_t)b * 9 * HW + (size_t)(oh * 2) * W + ow * 2;
        #pragma unroll
        for (int t = 0; t < 9; t++) kreg[t] = kp[(size_t)t * HW];
    } else {
        #pragma unroll
        for (int t = 0; t < 9; t++) kreg[t] = 1.0f;
    }

    u64 acc[8];
    #pragma unroll
    for (int p = 0; p < 8; p++) acc[p] = 0ull;

    for (int i = tid; i < 2 * CB * CSZ; i += 256) (&s_in[0][0])[i] = 0.0f;
    __syncthreads();

    const uint32_t sinA[2] = {(uint32_t)__cvta_generic_to_shared(&s_in[0][0]),
                              (uint32_t)__cvta_generic_to_shared(&s_in[1][0])};
    const uint32_t swA[2]  = {(uint32_t)__cvta_generic_to_shared(&s_w[0][0]),
                              (uint32_t)__cvta_generic_to_shared(&s_w[1][0])};
    const int NG = Ci / CB;
    const int gr0 = tY * 32 - 1;
    const int gc0 = tX * 32 - 4;

    const float* gsrc[NIT];
    uint32_t soff[NIT];
    bool sval[NIT];
    {
        const float* ib0 = in + (size_t)b * Ci * HW;
        #pragma unroll
        for (int k = 0; k < NIT; k++) {
            int slot = tid + k * 256;
            int c = slot / 330, rem = slot % 330;
            int r = rem / 10, q = rem % 10;
            int gr = gr0 + r, gc = gc0 + 4 * q;
            sval[k] = (slot < ISLOTS) && ((unsigned)gr < (unsigned)H) &&
                      (gc >= 0) && (gc + 4 <= W);
            soff[k] = (uint32_t)(c * CSZ + r * PITCH + 4 * q) * 4u;
            gsrc[k] = ib0 + (size_t)c * HW + (size_t)gr * W + gc;
        }
    }
    const bool wval = tid < CB * 36;
    uint32_t woff = 0;
    const float* wsrc = wt;
    {
        int c = tid / 36, rem = tid % 36, ij = rem / 4, q = rem % 4;
        woff = (uint32_t)(c * 144 + ij * 16 + 4 * q) * 4u;
        wsrc = wt + ((size_t)c * 9 + ij) * Co + (size_t)ocg * 16 + 4 * q;
    }
    const size_t gstep = (size_t)CB * HW;
    const size_t wstep = (size_t)CB * 9 * Co;

    auto stage = [&](int buf) {
        #pragma unroll
        for (int k = 0; k < NIT; k++) {
            if (sval[k]) cp_async16(sinA[buf] + soff[k], gsrc[k]);
            gsrc[k] += gstep;
        }
        if (wval) { cp_async16(swA[buf] + woff, wsrc); }
        wsrc += wstep;
    };

    stage(0);
    CP_COMMIT();

    const int base_off = (2 * ty) * PITCH + 2 * tx + 3;

    for (int cg = 0; cg < NG; cg++) {
        CP_WAIT0();
        __syncthreads();
        if (cg + 1 < NG) { stage((cg + 1) & 1); CP_COMMIT(); }
        const int buf = cg & 1;

        #pragma unroll
        for (int c = 0; c < CB; c++) {
            const float* sp = &s_in[buf][c * CSZ + base_off];
            const ulonglong2* wq = reinterpret_cast<const ulonglong2*>(&s_w[buf][c * 144]);
            #pragma unroll
            for (int t = 0; t < 9; t++) {
                float v = sp[(t / 3) * PITCH + (t % 3)] * kreg[t];
                u64 vv;
                PACK2(vv, v, v);
                TAP16(wq, t, vv, acc);
            }
        }
    }

    #pragma unroll
    for (int p = 0; p < 8; p++) {
        int o = ocg * 16 + 2 * p;
        float lo, hi;
        UNPACK2(lo, hi, acc[p]);
        float v0 = lo + bias[o], v1 = hi + bias[o + 1];
        v0 = v0 > 0.0f ? v0 : 0.0f;
        v1 = v1 > 0.0f ? v1 : 0.0f;
        out[((size_t)(b * Co + o)     * Hout + oh) * Wout + ow] = v0;
        out[((size_t)(b * Co + o + 1) * Hout + oh) * Wout + ow] = v1;
    }
}

__global__ void pac_gauss_kernel(const float* __restrict__ f, float* __restrict__ out,
                                 int C, int H, int W, float coeff2)
{
    const int b = blockIdx.z;
    const int idx = blockIdx.x * blockDim.x + threadIdx.x;
    if (idx >= H * W) return;
    const int h = idx / W, w = idx % W;

    float acc[9];
    #pragma unroll
    for (int t = 0; t < 9; t++) acc[t] = 0.0f;

    const float* fb = f + (size_t)b * C * H * W;
    for (int c = 0; c < C; c++) {
        const float* fc = fb + (size_t)c * H * W;
        float ctr = fc[idx];
        #pragma unroll
        for (int i = 0; i < 3; i++)
        #pragma unroll
        for (int j = 0; j < 3; j++) {
            int hh = h + i - 1, ww = w + j - 1;
            float nb = (hh >= 0 && hh < H && ww >= 0 && ww < W) ? fc[hh * W + ww] : 0.0f;
            float d = nb - ctr;
            acc[i * 3 + j] += d * d;
        }
    }

    float* ob = out + (size_t)b * 9 * H * W;
    #pragma unroll
    for (int t = 0; t < 9; t++)
        ob[(size_t)t * H * W + idx] = expf(-0.5f * coeff2 * acc[t]);
}

// ─── host side ───

static void conv_s1_l(const float* in, const float* wt, const float* b, const float* kern,
                      float* out, int Ci, int Co, int H, int W)
{
    if (W >= 32) {
        int tilesX = W / 32;
        dim3 grid(tilesX * (H / 16), Co / 16, 2);
        if (Ci % 4 == 0)
            conv_s1<4><<<grid, 256>>>(in, wt, b, kern, out, Ci, Co, H, W, tilesX);
        else
            conv_s1<1><<<grid, 256>>>(in, wt, b, kern, out, Ci, Co, H, W, tilesX);
    } else {
        dim3 grid(1, Co / 16, 2);
        conv_s1_16<<<grid, 256>>>(in, wt, b, kern, out, Ci, Co);
    }
}

static void conv_s2_l(const float* in, const float* wt, const float* b, const float* kern,
                      float* out, int Ci, int Co, int H, int W)
{
    int tilesX = W / 32;
    dim3 grid(tilesX * (H / 32), Co / 16, 2);
    conv_s2<<<grid, 256>>>(in, wt, b, kern, out, Ci, Co, H, W, tilesX);
}

static void pac_layer(const float* f, float* out, int C, int H, int W, float coeff2)
{
    int hw = H * W;
    dim3 grid((hw + 255) / 256, 1, 2);
    pac_gauss_kernel<<<grid, 256>>>(f, out, C, H, W, coeff2);
}

extern "C" void kernel_launch(void* const* d_in, const int* in_sizes, int n_in,
                              void* d_out, int out_size)
{
    const float* x = (const float*)d_in[0];
    WPtrs wp;
    const float* B14[14];
    for (int i = 0; i < 14; i++) {
        wp.p[i] = (const float*)d_in[1 + 2 * i];
        B14[i]  = (const float*)d_in[2 + 2 * i];
    }

    float* bufA; float* bufB; float* wT;
    cudaGetSymbolAddress((void**)&bufA, g_bufA);
    cudaGetSymbolAddress((void**)&bufB, g_bufB);
    cudaGetSymbolAddress((void**)&wT,  g_wT);

    static const size_t OFF[15] = {0,576,37440,74304,148032,295488,442944,737856,1327680,
                                   1917504,3097152,5456448,7815744,12534336,21971520};
    const float* wt[14];
    for (int l = 0; l < 14; l++) wt[l] = wT + OFF[l];

    transpose_all_kernel<<<(21971520 + 255) / 256, 256>>>(wp, wT);

    float* out = (float*)d_out;
    float* h1 = out;
    float* h2 = h1 + 8388608;
    float* h3 = h2 + 4194304;
    float* h4 = h3 + 2097152;
    float* h5 = h4 + 1048576;
    float* k2 = h5 + 524288;
    float* k3 = k2 + 294912;
    float* k4 = k3 + 73728;
    float* k5 = k4 + 18432;

    const float KC2 = 1e-4f * 1e-4f;

    // Stage 1
    conv_s1_l(x,    wt[0], B14[0], nullptr, bufA, 1,  64, 256, 256);
    conv_s1_l(bufA, wt[1], B14[1], nullptr, h1,   64, 64, 256, 256);
    conv_s2_l(h1,   wt[2], B14[2], nullptr, bufA, 64, 64, 256, 256);   // -> 2,64,128,128

    // Stage 2
    pac_layer(bufA, k2, 64, 128, 128, KC2);
    conv_s1_l(bufA, wt[3], B14[3], k2, bufB, 64,  128, 128, 128);
    conv_s1_l(bufB, wt[4], B14[4], k2, h2,   128, 128, 128, 128);
    conv_s2_l(h2,   wt[5], B14[5], k2, bufA, 128, 128, 128, 128);      // -> 2,128,64,64

    // Stage 3
    pac_layer(bufA, k3, 128, 64, 64, KC2);
    conv_s1_l(bufA, wt[6], B14[6], k3, bufB, 128, 256, 64, 64);
    conv_s1_l(bufB, wt[7], B14[7], k3, h3,   256, 256, 64, 64);
    conv_s2_l(h3,   wt[8], B14[8], k3, bufA, 256, 256, 64, 64);        // -> 2,256,32,32

    // Stage 4 (guidance h4*2 -> coeff^2 = 4)
    pac_layer(bufA, k4, 256, 32, 32, 4.0f);
    conv_s1_l(bufA, wt[9],  B14[9],  k4, bufB, 256, 512, 32, 32);
    conv_s1_l(bufB, wt[10], B14[10], k4, h4,   512, 512, 32, 32);
    conv_s2_l(h4,   wt[11], B14[11], k4, bufA, 512, 512, 32, 32);      // -> 2,512,16,16

    // Stage 5
    pac_layer(bufA, k5, 512, 16, 16, KC2);
    conv_s1_l(bufA, wt[12], B14[12], k5, bufB, 512,  1024, 16, 16);
    conv_s1_l(bufB, wt[13], B14[13], k5, h5,   1024, 1024, 16, 16);
}